// round 4
// baseline (speedup 1.0000x reference)
#include <cuda_runtime.h>
#include <math.h>

// Problem constants (fixed by setup_inputs): B=2, N=6890, NF=2000
#define B_    2
#define NMAX  7168
#define NFMAX 2048
#define WCH   8        // triangle chunks for winding (250 tris/chunk)
#define WFPC  256      // max tris per chunk staged in smem
#define MCH   8        // point chunks for minsq
#define NB1   32       // stage-1 reduce blocks per segment
#define BIGF  3.4e38f

typedef unsigned long long ull;

// -------- device scratch (no allocations allowed) --------
// points as float4 (x,y,z,|p|^2): [cloud][b*N+n]
__device__ float4 g_pts4[2][B_ * NMAX];
// triangles SoA: [src][ (b*13 + comp)*NFMAX + f ]
// comps: 0-2 A, 3-5 B, 6-8 C, 9-11 n=(B-A)x(C-A), 12 d0=A.n
__device__ float g_triS[2][B_ * 13 * NFMAX];
// partial atan2 sums: [chunk][seg*NMAX + n], seg = dir*2 + b
__device__ float g_wpart[WCH][4 * NMAX];
// partial (|q|^2 - 2 p.q + |p|^2) mins: [chunk][seg*NMAX + n]
__device__ float g_mpart[MCH][4 * NMAX];
// stage-1 reduction partials: [seg][block] = (mn, mx, sum, cnt)
__device__ float4 g_red[4][NB1];

// ---------------- packed f32x2 helpers (sm_100+) ----------------
__device__ __forceinline__ ull pk2(float lo, float hi) {
    ull r;
    asm("mov.b64 %0, {%1, %2};" : "=l"(r)
        : "r"(__float_as_uint(lo)), "r"(__float_as_uint(hi)));
    return r;
}
__device__ __forceinline__ float2 unpk2(ull v) {
    unsigned int lo, hi;
    asm("mov.b64 {%0, %1}, %2;" : "=r"(lo), "=r"(hi) : "l"(v));
    return make_float2(__uint_as_float(lo), __uint_as_float(hi));
}
__device__ __forceinline__ ull fma2(ull a, ull b, ull c) {
    ull d; asm("fma.rn.f32x2 %0, %1, %2, %3;" : "=l"(d) : "l"(a), "l"(b), "l"(c)); return d;
}
__device__ __forceinline__ ull add2(ull a, ull b) {
    ull d; asm("add.rn.f32x2 %0, %1, %2;" : "=l"(d) : "l"(a), "l"(b)); return d;
}
__device__ __forceinline__ ull mul2(ull a, ull b) {
    ull d; asm("mul.rn.f32x2 %0, %1, %2;" : "=l"(d) : "l"(a), "l"(b)); return d;
}
__device__ __forceinline__ float sqrt_ap(float x) {
    float r; asm("sqrt.approx.f32 %0, %1;" : "=f"(r) : "f"(x)); return r;
}

// ---------------------------------------------------------
// fast atan2: minimax odd polynomial on [0,1], abs err ~6e-7
// ---------------------------------------------------------
__device__ __forceinline__ float fast_atan2f(float y, float x) {
    float ax = fabsf(x), ay = fabsf(y);
    float mx = fmaxf(ax, ay);
    float mn = fminf(ax, ay);
    if (mx == 0.0f) return 0.0f;
    float t = __fdividef(mn, mx);
    float s = t * t;
    float p = fmaf(s, -0.01172120f, 0.05265332f);
    p = fmaf(s, p, -0.11643287f);
    p = fmaf(s, p,  0.19354346f);
    p = fmaf(s, p, -0.33262347f);
    p = fmaf(s, p,  0.99997726f);
    float r = p * t;
    if (ay > ax)  r = 1.57079632679f - r;
    if (x < 0.0f) r = 3.14159265359f - r;
    return (y < 0.0f) ? -r : r;
}

// ---------------------------------------------------------
// gather: float4 points (with |p|^2), triangle SoA + normal + d0
// ---------------------------------------------------------
__global__ void gather_kernel(const float* __restrict__ v1,
                              const float* __restrict__ v2,
                              const int*   __restrict__ faces,
                              int N, int NF) {
    int stride = gridDim.x * blockDim.x;
    int t0 = blockIdx.x * blockDim.x + threadIdx.x;

    int PT = B_ * N;
    for (int i = t0; i < PT; i += stride) {
        float x = v1[i * 3 + 0], y = v1[i * 3 + 1], z = v1[i * 3 + 2];
        g_pts4[0][i] = make_float4(x, y, z, fmaf(x, x, fmaf(y, y, z * z)));
        x = v2[i * 3 + 0]; y = v2[i * 3 + 1]; z = v2[i * 3 + 2];
        g_pts4[1][i] = make_float4(x, y, z, fmaf(x, x, fmaf(y, y, z * z)));
    }

    int FT = B_ * NF;
    for (int i = t0; i < FT; i += stride) {
        int b = i / NF;
        int f = i - b * NF;
        int i0 = faces[f * 3 + 0];
        int i1 = faces[f * 3 + 1];
        int i2 = faces[f * 3 + 2];
        int base = b * N * 3;
        #pragma unroll
        for (int s = 0; s < 2; s++) {
            const float* v = (s == 0) ? v1 : v2;
            float Ax = v[base + i0 * 3 + 0], Ay = v[base + i0 * 3 + 1], Az = v[base + i0 * 3 + 2];
            float Bx = v[base + i1 * 3 + 0], By = v[base + i1 * 3 + 1], Bz = v[base + i1 * 3 + 2];
            float Cx = v[base + i2 * 3 + 0], Cy = v[base + i2 * 3 + 1], Cz = v[base + i2 * 3 + 2];
            float ex = Bx - Ax, ey = By - Ay, ez = Bz - Az;
            float fx = Cx - Ax, fy = Cy - Ay, fz = Cz - Az;
            float nx = fmaf(ey, fz, -ez * fy);
            float ny = fmaf(ez, fx, -ex * fz);
            float nz = fmaf(ex, fy, -ey * fx);
            float d0 = fmaf(Ax, nx, fmaf(Ay, ny, Az * nz));
            float* T = g_triS[s] + (size_t)(b * 13) * NFMAX + f;
            T[0 * NFMAX] = Ax;  T[1 * NFMAX] = Ay;  T[2 * NFMAX] = Az;
            T[3 * NFMAX] = Bx;  T[4 * NFMAX] = By;  T[5 * NFMAX] = Bz;
            T[6 * NFMAX] = Cx;  T[7 * NFMAX] = Cy;  T[8 * NFMAX] = Cz;
            T[9 * NFMAX] = nx;  T[10 * NFMAX] = ny; T[11 * NFMAX] = nz;
            T[12 * NFMAX] = d0;
        }
    }
}

// ---------------------------------------------------------
// winding: 2 points per thread packed in f32x2 lanes.
// Triangle chunk staged in smem as duplicated (v,v) pairs so
// FFMA2 operands come straight from LDS.64 (no packing movs).
// grid: x covers H=ceil(N/2) threads, y = seg*WCH + chunk (seg = dir*2+b)
// ---------------------------------------------------------
__global__ void __launch_bounds__(256)
winding_kernel(int N, int NF) {
    __shared__ ull smT[13][WFPC];

    int yc = blockIdx.y;
    int seg = yc >> 3;          // dir*2 + b
    int chunk = yc & 7;
    int dir = seg >> 1;
    int b = seg & 1;
    int H = (N + 1) >> 1;
    int t = blockIdx.x * 256 + threadIdx.x;

    int src = 1 - dir;
    int fpc = (NF + WCH - 1) / WCH;
    int f0 = chunk * fpc;
    int f1 = min(NF, f0 + fpc);
    int nf = f1 - f0;           // <= WFPC

    // cooperative stage: duplicated-pair layout
    {
        const float* Tb = g_triS[src] + (size_t)(b * 13) * NFMAX + f0;
        #pragma unroll
        for (int c = 0; c < 13; c++) {
            for (int j = threadIdx.x; j < nf; j += 256) {
                float v = Tb[c * NFMAX + j];
                smT[c][j] = pk2(v, v);
            }
        }
    }
    __syncthreads();

    if (t >= H) return;

    const float4* __restrict__ P = g_pts4[dir] + b * N;
    int i0 = t, i1 = t + H;
    bool ok1 = (i1 < N);
    float4 p0 = P[i0];
    float4 p1 = ok1 ? P[i1] : p0;

    // packed negated point coords
    ull npx = pk2(-p0.x, -p1.x);
    ull npy = pk2(-p0.y, -p1.y);
    ull npz = pk2(-p0.z, -p1.z);

    float acc0 = 0.0f, acc1 = 0.0f;
    for (int j = 0; j < nf; ++j) {
        ull ax = add2(smT[0][j], npx);
        ull ay = add2(smT[1][j], npy);
        ull az = add2(smT[2][j], npz);
        ull bx = add2(smT[3][j], npx);
        ull by = add2(smT[4][j], npy);
        ull bz = add2(smT[5][j], npz);
        ull cx = add2(smT[6][j], npx);
        ull cy = add2(smT[7][j], npy);
        ull cz = add2(smT[8][j], npz);

        ull a2 = fma2(ax, ax, fma2(ay, ay, mul2(az, az)));
        ull b2 = fma2(bx, bx, fma2(by, by, mul2(bz, bz)));
        ull c2 = fma2(cx, cx, fma2(cy, cy, mul2(cz, cz)));

        // det = d0 - p.n  (np = -p)
        ull det = fma2(npx, smT[9][j],
                  fma2(npy, smT[10][j],
                  fma2(npz, smT[11][j], smT[12][j])));

        ull dab = fma2(ax, bx, fma2(ay, by, mul2(az, bz)));
        ull dbc = fma2(bx, cx, fma2(by, cy, mul2(bz, cz)));
        ull dca = fma2(cx, ax, fma2(cy, ay, mul2(cz, az)));

        float2 a2s = unpk2(a2), b2s = unpk2(b2), c2s = unpk2(c2);
        float2 dets = unpk2(det);
        float2 dabs = unpk2(dab), dbcs = unpk2(dbc), dcas = unpk2(dca);

        float la0 = sqrt_ap(a2s.x), lb0 = sqrt_ap(b2s.x), lc0 = sqrt_ap(c2s.x);
        float la1 = sqrt_ap(a2s.y), lb1 = sqrt_ap(b2s.y), lc1 = sqrt_ap(c2s.y);

        float den0 = fmaf(la0 * lb0, lc0, fmaf(dabs.x, lc0, fmaf(dbcs.x, la0, dcas.x * lb0)));
        float den1 = fmaf(la1 * lb1, lc1, fmaf(dabs.y, lc1, fmaf(dbcs.y, la1, dcas.y * lb1)));

        acc0 += fast_atan2f(dets.x, den0);
        acc1 += fast_atan2f(dets.y, den1);
    }
    int base = seg * NMAX;
    g_wpart[chunk][base + i0] = acc0;
    if (ok1) g_wpart[chunk][base + i1] = acc1;
}

// ---------------------------------------------------------
// minsq: 4 scalar points per thread vs packed pairs of q.
// grid: x covers Q=ceil(N/4), y = seg_local*MCH + chunk; seg = seg_base+seg_local
// ---------------------------------------------------------
__global__ void __launch_bounds__(256, 2)
minsq_kernel(int N, int seg_base) {
    int yc = blockIdx.y;
    int seg = seg_base + (yc >> 3);
    int chunk = yc & 7;
    int dir = seg >> 1;
    int b = seg & 1;
    int Q = (N + 3) >> 2;
    int t = blockIdx.x * 256 + threadIdx.x;
    if (t >= Q) return;

    const float4* __restrict__ P = g_pts4[dir] + b * N;
    const float4* __restrict__ O = g_pts4[1 - dir] + b * N;

    int i0 = t, i1 = t + Q, i2 = t + 2 * Q, i3 = t + 3 * Q;
    bool ok1 = (i1 < N), ok2 = (i2 < N), ok3 = (i3 < N);
    float4 p0 = P[i0];
    float4 p1 = ok1 ? P[i1] : p0;
    float4 p2 = ok2 ? P[i2] : p0;
    float4 p3 = ok3 ? P[i3] : p0;

    ull p0x = pk2(p0.x, p0.x), p0y = pk2(p0.y, p0.y), p0z = pk2(p0.z, p0.z);
    ull p1x = pk2(p1.x, p1.x), p1y = pk2(p1.y, p1.y), p1z = pk2(p1.z, p1.z);
    ull p2x = pk2(p2.x, p2.x), p2y = pk2(p2.y, p2.y), p2z = pk2(p2.z, p2.z);
    ull p3x = pk2(p3.x, p3.x), p3y = pk2(p3.y, p3.y), p3z = pk2(p3.z, p3.z);
    ull m2  = pk2(-2.0f, -2.0f);

    int mpc = (N + MCH - 1) / MCH;
    int m0 = chunk * mpc;
    int m1 = min(N, m0 + mpc);

    float b0 = BIGF, b1v = BIGF, b2v = BIGF, b3v = BIGF;
    int m = m0;
    for (; m + 1 < m1; m += 2) {
        float4 qa = O[m];
        float4 qb = O[m + 1];
        ull qx = pk2(qa.x, qb.x);
        ull qy = pk2(qa.y, qb.y);
        ull qz = pk2(qa.z, qb.z);
        ull qw = pk2(qa.w, qb.w);

        ull d0 = fma2(p0x, qx, fma2(p0y, qy, mul2(p0z, qz)));
        ull d1 = fma2(p1x, qx, fma2(p1y, qy, mul2(p1z, qz)));
        ull d2 = fma2(p2x, qx, fma2(p2y, qy, mul2(p2z, qz)));
        ull d3 = fma2(p3x, qx, fma2(p3y, qy, mul2(p3z, qz)));
        float2 v0 = unpk2(fma2(m2, d0, qw));
        float2 v1 = unpk2(fma2(m2, d1, qw));
        float2 v2 = unpk2(fma2(m2, d2, qw));
        float2 v3 = unpk2(fma2(m2, d3, qw));
        b0  = fminf(b0,  fminf(v0.x, v0.y));
        b1v = fminf(b1v, fminf(v1.x, v1.y));
        b2v = fminf(b2v, fminf(v2.x, v2.y));
        b3v = fminf(b3v, fminf(v3.x, v3.y));
    }
    for (; m < m1; ++m) {
        float4 q = O[m];
        float d0 = fmaf(p0.x, q.x, fmaf(p0.y, q.y, p0.z * q.z));
        float d1 = fmaf(p1.x, q.x, fmaf(p1.y, q.y, p1.z * q.z));
        float d2 = fmaf(p2.x, q.x, fmaf(p2.y, q.y, p2.z * q.z));
        float d3 = fmaf(p3.x, q.x, fmaf(p3.y, q.y, p3.z * q.z));
        b0  = fminf(b0,  fmaf(-2.0f, d0, q.w));
        b1v = fminf(b1v, fmaf(-2.0f, d1, q.w));
        b2v = fminf(b2v, fmaf(-2.0f, d2, q.w));
        b3v = fminf(b3v, fmaf(-2.0f, d3, q.w));
    }
    int base = seg * NMAX;
    g_mpart[chunk][base + i0] = b0 + p0.w;
    if (ok1) g_mpart[chunk][base + i1] = b1v + p1.w;
    if (ok2) g_mpart[chunk][base + i2] = b2v + p2.w;
    if (ok3) g_mpart[chunk][base + i3] = b3v + p3.w;
}

// ---------------------------------------------------------
// stage-1 reduce: grid (NB1, 4 segs); per-block partial stats
// ---------------------------------------------------------
__global__ void __launch_bounds__(256)
reduce1_kernel(int N) {
    __shared__ float sh[8][4];
    const float INV2PI = 0.15915494309189535f;
    int seg = blockIdx.y;
    int per = (N + NB1 - 1) / NB1;
    int n0 = blockIdx.x * per;
    int n1 = min(N, n0 + per);
    int tid = threadIdx.x;
    int lane = tid & 31;
    int warp = tid >> 5;

    float mn = BIGF, mx = -BIGF, s = 0.0f, c = 0.0f;
    for (int n = n0 + tid; n < n1; n += 256) {
        int ia = seg * NMAX + n;
        float w = 0.0f, ms = BIGF;
        #pragma unroll
        for (int ch = 0; ch < WCH; ch++) {
            w += g_wpart[ch][ia];
            ms = fminf(ms, g_mpart[ch][ia]);
        }
        float rm = sqrtf(fmaxf(ms, 0.0f));
        mn = fminf(mn, rm);
        if (w * INV2PI >= 0.99f) { mx = fmaxf(mx, rm); s += rm; c += 1.0f; }
    }
    #pragma unroll
    for (int o = 16; o; o >>= 1) {
        mn = fminf(mn, __shfl_xor_sync(0xffffffffu, mn, o));
        mx = fmaxf(mx, __shfl_xor_sync(0xffffffffu, mx, o));
        s +=           __shfl_xor_sync(0xffffffffu, s,  o);
        c +=           __shfl_xor_sync(0xffffffffu, c,  o);
    }
    if (lane == 0) { sh[warp][0] = mn; sh[warp][1] = mx; sh[warp][2] = s; sh[warp][3] = c; }
    __syncthreads();
    if (tid == 0) {
        #pragma unroll
        for (int w = 1; w < 8; w++) {
            mn = fminf(mn, sh[w][0]);
            mx = fmaxf(mx, sh[w][1]);
            s += sh[w][2];
            c += sh[w][3];
        }
        g_red[seg][blockIdx.x] = make_float4(mn, mx, s, c);
    }
}

// ---------------------------------------------------------
// stage-2 reduce: 4 warps, one per seg; lanes over NB1 blocks
// out layout: [5][B] row-major
// ---------------------------------------------------------
__global__ void __launch_bounds__(128)
reduce2_kernel(float* __restrict__ out) {
    __shared__ float sh[4][4];
    int tid = threadIdx.x;
    int lane = tid & 31;
    int seg = tid >> 5;

    float4 v = g_red[seg][lane];   // NB1 == 32
    float mn = v.x, mx = v.y, s = v.z, c = v.w;
    #pragma unroll
    for (int o = 16; o; o >>= 1) {
        mn = fminf(mn, __shfl_xor_sync(0xffffffffu, mn, o));
        mx = fmaxf(mx, __shfl_xor_sync(0xffffffffu, mx, o));
        s +=           __shfl_xor_sync(0xffffffffu, s,  o);
        c +=           __shfl_xor_sync(0xffffffffu, c,  o);
    }
    if (lane == 0) { sh[seg][0] = mn; sh[seg][1] = mx; sh[seg][2] = s; sh[seg][3] = c; }
    __syncthreads();
    if (tid < B_) {
        int b = tid;
        float mn0 = sh[b][0];
        float mx1 = sh[b][1], s1 = sh[b][2], c1 = sh[b][3];
        float mx2 = sh[2 + b][1], s2 = sh[2 + b][2], c2 = sh[2 + b][3];
        out[0 * B_ + b] = mn0;
        out[1 * B_ + b] = (c1 > 0.0f) ? mx1 : 0.0f;
        out[2 * B_ + b] = (c1 > 0.0f) ? s1 / fmaxf(c1, 1.0f) : 0.0f;
        out[3 * B_ + b] = (c2 > 0.0f) ? mx2 : 0.0f;
        out[4 * B_ + b] = (c2 > 0.0f) ? s2 / fmaxf(c2, 1.0f) : 0.0f;
    }
}

// ---------------------------------------------------------
extern "C" void kernel_launch(void* const* d_in, const int* in_sizes, int n_in,
                              void* d_out, int out_size) {
    const float* v1 = (const float*)d_in[0];
    const float* v2 = (const float*)d_in[1];
    const int* faces = (const int*)d_in[2];
    float* out = (float*)d_out;

    int N = in_sizes[0] / (3 * B_);   // 6890
    int NF = in_sizes[2] / 3;         // 2000

    int gwork = B_ * N;
    if (B_ * NF > gwork) gwork = B_ * NF;
    gather_kernel<<<(gwork + 255) / 256, 256>>>(v1, v2, faces, N, NF);

    // minsq split into two launches (segs 0-1, then 2-3) so winding is the
    // 4th launch (the slot ncu has been capturing).
    int Q = (N + 3) >> 2;
    dim3 mgrid((Q + 255) / 256, 2 * MCH);
    minsq_kernel<<<mgrid, 256>>>(N, 0);
    minsq_kernel<<<mgrid, 256>>>(N, 2);

    int H = (N + 1) >> 1;
    dim3 wgrid((H + 255) / 256, 4 * WCH);
    winding_kernel<<<wgrid, 256>>>(N, NF);

    dim3 rgrid(NB1, 4);
    reduce1_kernel<<<rgrid, 256>>>(N);
    reduce2_kernel<<<1, 128>>>(out);
}

// round 5
// speedup vs baseline: 1.2027x; 1.2027x over previous
#include <cuda_runtime.h>
#include <math.h>

// Problem constants (fixed by setup_inputs): B=2, N=6890, NF=2000
#define B_    2
#define NMAX  7168
#define NFMAX 2048
#define WCH   16       // triangle chunks for winding (125 tris/chunk)
#define WFPC  128      // max tris per chunk staged in smem
#define MCH   8        // point chunks for minsq
#define NB1   32       // stage-1 reduce blocks per segment
#define BIGF  3.4e38f

typedef unsigned long long ull;

// -------- device scratch (no allocations allowed) --------
// points as float4 (x,y,z,|p|^2): [cloud][b*N+n]
__device__ float4 g_pts4[2][B_ * NMAX];
// triangles SoA: [src][ (b*13 + comp)*NFMAX + f ]
// comps: 0-2 A, 3-5 B, 6-8 C, 9-11 n=(B-A)x(C-A), 12 d0=A.n
__device__ float g_triS[2][B_ * 13 * NFMAX];
// partial atan2 sums: [chunk][seg*NMAX + n], seg = dir*2 + b
__device__ float g_wpart[WCH][4 * NMAX];
// partial (|q|^2 - 2 p.q + |p|^2) mins: [chunk][seg*NMAX + n]
__device__ float g_mpart[MCH][4 * NMAX];
// stage-1 reduction partials: [seg][block] = (mn, mx, sum, cnt)
__device__ float4 g_red[4][NB1];

// ---------------- packed f32x2 helpers (sm_100+) ----------------
__device__ __forceinline__ ull pk2(float lo, float hi) {
    ull r;
    asm("mov.b64 %0, {%1, %2};" : "=l"(r)
        : "r"(__float_as_uint(lo)), "r"(__float_as_uint(hi)));
    return r;
}
__device__ __forceinline__ float2 unpk2(ull v) {
    unsigned int lo, hi;
    asm("mov.b64 {%0, %1}, %2;" : "=r"(lo), "=r"(hi) : "l"(v));
    return make_float2(__uint_as_float(lo), __uint_as_float(hi));
}
__device__ __forceinline__ ull fma2(ull a, ull b, ull c) {
    ull d; asm("fma.rn.f32x2 %0, %1, %2, %3;" : "=l"(d) : "l"(a), "l"(b), "l"(c)); return d;
}
__device__ __forceinline__ ull add2(ull a, ull b) {
    ull d; asm("add.rn.f32x2 %0, %1, %2;" : "=l"(d) : "l"(a), "l"(b)); return d;
}
__device__ __forceinline__ ull mul2(ull a, ull b) {
    ull d; asm("mul.rn.f32x2 %0, %1, %2;" : "=l"(d) : "l"(a), "l"(b)); return d;
}
__device__ __forceinline__ float sqrt_ap(float x) {
    float r; asm("sqrt.approx.f32 %0, %1;" : "=f"(r) : "f"(x)); return r;
}

// ---------------------------------------------------------
// gather A: float4 points (with |p|^2)
// ---------------------------------------------------------
__global__ void gather_pts_kernel(const float* __restrict__ v1,
                                  const float* __restrict__ v2,
                                  int N) {
    int stride = gridDim.x * blockDim.x;
    int t0 = blockIdx.x * blockDim.x + threadIdx.x;
    int PT = B_ * N;
    for (int i = t0; i < PT; i += stride) {
        float x = v1[i * 3 + 0], y = v1[i * 3 + 1], z = v1[i * 3 + 2];
        g_pts4[0][i] = make_float4(x, y, z, fmaf(x, x, fmaf(y, y, z * z)));
        x = v2[i * 3 + 0]; y = v2[i * 3 + 1]; z = v2[i * 3 + 2];
        g_pts4[1][i] = make_float4(x, y, z, fmaf(x, x, fmaf(y, y, z * z)));
    }
}

// ---------------------------------------------------------
// gather B: triangle SoA + normal + d0
// ---------------------------------------------------------
__global__ void gather_tri_kernel(const float* __restrict__ v1,
                                  const float* __restrict__ v2,
                                  const int*   __restrict__ faces,
                                  int N, int NF) {
    int stride = gridDim.x * blockDim.x;
    int t0 = blockIdx.x * blockDim.x + threadIdx.x;
    int FT = B_ * NF;
    for (int i = t0; i < FT; i += stride) {
        int b = i / NF;
        int f = i - b * NF;
        int i0 = faces[f * 3 + 0];
        int i1 = faces[f * 3 + 1];
        int i2 = faces[f * 3 + 2];
        int base = b * N * 3;
        #pragma unroll
        for (int s = 0; s < 2; s++) {
            const float* v = (s == 0) ? v1 : v2;
            float Ax = v[base + i0 * 3 + 0], Ay = v[base + i0 * 3 + 1], Az = v[base + i0 * 3 + 2];
            float Bx = v[base + i1 * 3 + 0], By = v[base + i1 * 3 + 1], Bz = v[base + i1 * 3 + 2];
            float Cx = v[base + i2 * 3 + 0], Cy = v[base + i2 * 3 + 1], Cz = v[base + i2 * 3 + 2];
            float ex = Bx - Ax, ey = By - Ay, ez = Bz - Az;
            float fx = Cx - Ax, fy = Cy - Ay, fz = Cz - Az;
            float nx = fmaf(ey, fz, -ez * fy);
            float ny = fmaf(ez, fx, -ex * fz);
            float nz = fmaf(ex, fy, -ey * fx);
            float d0 = fmaf(Ax, nx, fmaf(Ay, ny, Az * nz));
            float* T = g_triS[s] + (size_t)(b * 13) * NFMAX + f;
            T[0 * NFMAX] = Ax;  T[1 * NFMAX] = Ay;  T[2 * NFMAX] = Az;
            T[3 * NFMAX] = Bx;  T[4 * NFMAX] = By;  T[5 * NFMAX] = Bz;
            T[6 * NFMAX] = Cx;  T[7 * NFMAX] = Cy;  T[8 * NFMAX] = Cz;
            T[9 * NFMAX] = nx;  T[10 * NFMAX] = ny; T[11 * NFMAX] = nz;
            T[12 * NFMAX] = d0;
        }
    }
}

// ---------------------------------------------------------
// minsq: 4 scalar points per thread vs packed pairs of q.
// grid: x covers Q=ceil(N/4), y = seg*MCH + chunk (seg = dir*2+b)
// ---------------------------------------------------------
__global__ void __launch_bounds__(256, 2)
minsq_kernel(int N) {
    int yc = blockIdx.y;
    int seg = yc >> 3;
    int chunk = yc & 7;
    int dir = seg >> 1;
    int b = seg & 1;
    int Q = (N + 3) >> 2;
    int t = blockIdx.x * 256 + threadIdx.x;
    if (t >= Q) return;

    const float4* __restrict__ P = g_pts4[dir] + b * N;
    const float4* __restrict__ O = g_pts4[1 - dir] + b * N;

    int i0 = t, i1 = t + Q, i2 = t + 2 * Q, i3 = t + 3 * Q;
    bool ok1 = (i1 < N), ok2 = (i2 < N), ok3 = (i3 < N);
    float4 p0 = P[i0];
    float4 p1 = ok1 ? P[i1] : p0;
    float4 p2 = ok2 ? P[i2] : p0;
    float4 p3 = ok3 ? P[i3] : p0;

    ull p0x = pk2(p0.x, p0.x), p0y = pk2(p0.y, p0.y), p0z = pk2(p0.z, p0.z);
    ull p1x = pk2(p1.x, p1.x), p1y = pk2(p1.y, p1.y), p1z = pk2(p1.z, p1.z);
    ull p2x = pk2(p2.x, p2.x), p2y = pk2(p2.y, p2.y), p2z = pk2(p2.z, p2.z);
    ull p3x = pk2(p3.x, p3.x), p3y = pk2(p3.y, p3.y), p3z = pk2(p3.z, p3.z);
    ull m2  = pk2(-2.0f, -2.0f);

    int mpc = (N + MCH - 1) / MCH;
    int m0 = chunk * mpc;
    int m1 = min(N, m0 + mpc);

    float b0 = BIGF, b1v = BIGF, b2v = BIGF, b3v = BIGF;
    int m = m0;
    for (; m + 1 < m1; m += 2) {
        float4 qa = O[m];
        float4 qb = O[m + 1];
        ull qx = pk2(qa.x, qb.x);
        ull qy = pk2(qa.y, qb.y);
        ull qz = pk2(qa.z, qb.z);
        ull qw = pk2(qa.w, qb.w);

        ull d0 = fma2(p0x, qx, fma2(p0y, qy, mul2(p0z, qz)));
        ull d1 = fma2(p1x, qx, fma2(p1y, qy, mul2(p1z, qz)));
        ull d2 = fma2(p2x, qx, fma2(p2y, qy, mul2(p2z, qz)));
        ull d3 = fma2(p3x, qx, fma2(p3y, qy, mul2(p3z, qz)));
        float2 v0 = unpk2(fma2(m2, d0, qw));
        float2 v1 = unpk2(fma2(m2, d1, qw));
        float2 v2 = unpk2(fma2(m2, d2, qw));
        float2 v3 = unpk2(fma2(m2, d3, qw));
        b0  = fminf(b0,  fminf(v0.x, v0.y));
        b1v = fminf(b1v, fminf(v1.x, v1.y));
        b2v = fminf(b2v, fminf(v2.x, v2.y));
        b3v = fminf(b3v, fminf(v3.x, v3.y));
    }
    for (; m < m1; ++m) {
        float4 q = O[m];
        float d0 = fmaf(p0.x, q.x, fmaf(p0.y, q.y, p0.z * q.z));
        float d1 = fmaf(p1.x, q.x, fmaf(p1.y, q.y, p1.z * q.z));
        float d2 = fmaf(p2.x, q.x, fmaf(p2.y, q.y, p2.z * q.z));
        float d3 = fmaf(p3.x, q.x, fmaf(p3.y, q.y, p3.z * q.z));
        b0  = fminf(b0,  fmaf(-2.0f, d0, q.w));
        b1v = fminf(b1v, fmaf(-2.0f, d1, q.w));
        b2v = fminf(b2v, fmaf(-2.0f, d2, q.w));
        b3v = fminf(b3v, fmaf(-2.0f, d3, q.w));
    }
    int base = seg * NMAX;
    g_mpart[chunk][base + i0] = b0 + p0.w;
    if (ok1) g_mpart[chunk][base + i1] = b1v + p1.w;
    if (ok2) g_mpart[chunk][base + i2] = b2v + p2.w;
    if (ok3) g_mpart[chunk][base + i3] = b3v + p3.w;
}

// ---------------------------------------------------------
// packed atan2 for a pair: poly in f32x2, range reduction scalar
// returns pk2(atan2(d.x, n.x), atan2(d.y, n.y))
// ---------------------------------------------------------
__device__ __forceinline__ ull atan2_pair(ull det, ull den,
                                          ull C4, ull C3, ull C2, ull C1, ull C0) {
    float2 d = unpk2(det), n = unpk2(den);

    float ax0 = fabsf(n.x), ay0 = fabsf(d.x);
    float mx0 = fmaxf(ax0, ay0), mn0 = fminf(ax0, ay0);
    float t0 = (mx0 > 0.0f) ? __fdividef(mn0, mx0) : 0.0f;
    float ax1 = fabsf(n.y), ay1 = fabsf(d.y);
    float mx1 = fmaxf(ax1, ay1), mn1 = fminf(ax1, ay1);
    float t1 = (mx1 > 0.0f) ? __fdividef(mn1, mx1) : 0.0f;

    ull T = pk2(t0, t1);
    ull S = mul2(T, T);
    ull P = fma2(S, C4, C3);
    P = fma2(S, P, C2);
    P = fma2(S, P, C1);
    P = fma2(S, P, C0);
    ull R = mul2(P, T);
    float2 r = unpk2(R);

    float r0 = r.x;
    if (ay0 > ax0)   r0 = 1.57079632679f - r0;
    if (n.x < 0.0f)  r0 = 3.14159265359f - r0;
    if (d.x < 0.0f)  r0 = -r0;
    float r1 = r.y;
    if (ay1 > ax1)   r1 = 1.57079632679f - r1;
    if (n.y < 0.0f)  r1 = 3.14159265359f - r1;
    if (d.y < 0.0f)  r1 = -r1;
    return pk2(r0, r1);
}

// per-pair solid-angle core: all packed, returns packed atan2 pair
__device__ __forceinline__ ull wind_pair(
    ull npx, ull npy, ull npz,
    ull tAx, ull tAy, ull tAz,
    ull tBx, ull tBy, ull tBz,
    ull tCx, ull tCy, ull tCz,
    ull tnx, ull tny, ull tnz, ull td0,
    ull C4, ull C3, ull C2, ull C1, ull C0)
{
    ull ax = add2(tAx, npx), ay = add2(tAy, npy), az = add2(tAz, npz);
    ull bx = add2(tBx, npx), by = add2(tBy, npy), bz = add2(tBz, npz);
    ull cx = add2(tCx, npx), cy = add2(tCy, npy), cz = add2(tCz, npz);

    ull a2 = fma2(ax, ax, fma2(ay, ay, mul2(az, az)));
    ull b2 = fma2(bx, bx, fma2(by, by, mul2(bz, bz)));
    ull c2 = fma2(cx, cx, fma2(cy, cy, mul2(cz, cz)));

    // det = d0 - p.n  (np = -p)
    ull det = fma2(npx, tnx, fma2(npy, tny, fma2(npz, tnz, td0)));

    ull dab = fma2(ax, bx, fma2(ay, by, mul2(az, bz)));
    ull dbc = fma2(bx, cx, fma2(by, cy, mul2(bz, cz)));
    ull dca = fma2(cx, ax, fma2(cy, ay, mul2(cz, az)));

    float2 a2s = unpk2(a2), b2s = unpk2(b2), c2s = unpk2(c2);
    ull la = pk2(sqrt_ap(a2s.x), sqrt_ap(a2s.y));
    ull lb = pk2(sqrt_ap(b2s.x), sqrt_ap(b2s.y));
    ull lc = pk2(sqrt_ap(c2s.x), sqrt_ap(c2s.y));

    ull den = fma2(mul2(la, lb), lc,
              fma2(dab, lc,
              fma2(dbc, la, mul2(dca, lb))));

    return atan2_pair(det, den, C4, C3, C2, C1, C0);
}

// ---------------------------------------------------------
// winding: 4 points per thread as two f32x2 pairs; triangle chunk
// staged in smem as duplicated (v,v) pairs (LDS.64 operands).
// grid: x covers H4=ceil(N/4), y = seg*WCH + chunk (seg = dir*2+b)
// ---------------------------------------------------------
__global__ void __launch_bounds__(256)
winding_kernel(int N, int NF) {
    __shared__ ull smT[13][WFPC];

    int yc = blockIdx.y;
    int seg = yc >> 4;          // dir*2 + b
    int chunk = yc & 15;
    int dir = seg >> 1;
    int b = seg & 1;
    int H4 = (N + 3) >> 2;
    int t = blockIdx.x * 256 + threadIdx.x;

    int src = 1 - dir;
    int fpc = (NF + WCH - 1) / WCH;
    int f0 = chunk * fpc;
    int f1 = min(NF, f0 + fpc);
    int nf = f1 - f0;           // <= WFPC

    // cooperative stage: duplicated-pair layout
    {
        const float* Tb = g_triS[src] + (size_t)(b * 13) * NFMAX + f0;
        #pragma unroll
        for (int c = 0; c < 13; c++) {
            for (int j = threadIdx.x; j < nf; j += 256) {
                float v = Tb[c * NFMAX + j];
                smT[c][j] = pk2(v, v);
            }
        }
    }
    __syncthreads();

    if (t >= H4) return;

    const float4* __restrict__ P = g_pts4[dir] + b * N;
    int i0 = t, i1 = t + H4, i2 = t + 2 * H4, i3 = t + 3 * H4;
    bool ok3 = (i3 < N);   // i1,i2 always < N for our sizes; i3 may not be
    float4 p0 = P[i0];
    float4 p1 = P[i1];
    float4 p2 = P[i2];
    float4 p3 = ok3 ? P[i3] : p2;

    // packed negated point coords, pair A = (p0,p1), pair B = (p2,p3)
    ull nAx = pk2(-p0.x, -p1.x), nAy = pk2(-p0.y, -p1.y), nAz = pk2(-p0.z, -p1.z);
    ull nBx = pk2(-p2.x, -p3.x), nBy = pk2(-p2.y, -p3.y), nBz = pk2(-p2.z, -p3.z);

    ull C4 = pk2(-0.01172120f, -0.01172120f);
    ull C3 = pk2( 0.05265332f,  0.05265332f);
    ull C2 = pk2(-0.11643287f, -0.11643287f);
    ull C1 = pk2( 0.19354346f,  0.19354346f);
    ull C0 = pk2(-0.33262347f, -0.33262347f);
    ull CC = pk2( 0.99997726f,  0.99997726f);
    // fold last two coeffs: poly = ((((C4 s + C3) s + C2) s + C1) s + C0) s + CC
    // atan2_pair uses 5 coeffs; pass C3..CC shifted (C4 handled via first fma)
    (void)C0;

    ull accA = 0, accB = 0;
    for (int j = 0; j < nf; ++j) {
        ull tAx = smT[0][j], tAy = smT[1][j], tAz = smT[2][j];
        ull tBx = smT[3][j], tBy = smT[4][j], tBz = smT[5][j];
        ull tCx = smT[6][j], tCy = smT[7][j], tCz = smT[8][j];
        ull tnx = smT[9][j], tny = smT[10][j], tnz = smT[11][j];
        ull td0 = smT[12][j];

        // 6-coeff poly folded into atan2_pair via composing: pass the 5 lowest
        // (we evaluate C4 first inside). Full chain replicated here:
        {
            // pair A
            ull rA = wind_pair(nAx, nAy, nAz, tAx, tAy, tAz, tBx, tBy, tBz,
                               tCx, tCy, tCz, tnx, tny, tnz, td0,
                               C4, C3, C2, C1, C0);
            // rA currently missing CC term — handled inside atan2_pair? No:
            // atan2_pair computes 5-level Horner ending at C0 then *T; we need
            // one more level. Fix by noting atan2_pair's last coeff arg is C0;
            // we instead pass (C3,C2,C1,C0,CC) and pre-fold C4 outside? To keep
            // exactness with prior rounds, wind_pair/atan2_pair evaluate the
            // full 6-coefficient chain: see atan2_pair6 below.
            (void)rA;
        }
        break; // placeholder never executed; real loop below
    }

    // real loop (6-coeff correct path)
    for (int j = 0; j < nf; ++j) {
        ull tAx = smT[0][j], tAy = smT[1][j], tAz = smT[2][j];
        ull tBx = smT[3][j], tBy = smT[4][j], tBz = smT[5][j];
        ull tCx = smT[6][j], tCy = smT[7][j], tCz = smT[8][j];
        ull tnx = smT[9][j], tny = smT[10][j], tnz = smT[11][j];
        ull td0 = smT[12][j];

        {
            ull ax = add2(tAx, nAx), ay = add2(tAy, nAy), az = add2(tAz, nAz);
            ull bx = add2(tBx, nAx), by = add2(tBy, nAy), bz = add2(tBz, nAz);
            ull cx = add2(tCx, nAx), cy = add2(tCy, nAy), cz = add2(tCz, nAz);
            ull a2 = fma2(ax, ax, fma2(ay, ay, mul2(az, az)));
            ull b2 = fma2(bx, bx, fma2(by, by, mul2(bz, bz)));
            ull c2 = fma2(cx, cx, fma2(cy, cy, mul2(cz, cz)));
            ull det = fma2(nAx, tnx, fma2(nAy, tny, fma2(nAz, tnz, td0)));
            ull dab = fma2(ax, bx, fma2(ay, by, mul2(az, bz)));
            ull dbc = fma2(bx, cx, fma2(by, cy, mul2(bz, cz)));
            ull dca = fma2(cx, ax, fma2(cy, ay, mul2(cz, az)));
            float2 a2s = unpk2(a2), b2s = unpk2(b2), c2s = unpk2(c2);
            ull la = pk2(sqrt_ap(a2s.x), sqrt_ap(a2s.y));
            ull lb = pk2(sqrt_ap(b2s.x), sqrt_ap(b2s.y));
            ull lc = pk2(sqrt_ap(c2s.x), sqrt_ap(c2s.y));
            ull den = fma2(mul2(la, lb), lc, fma2(dab, lc, fma2(dbc, la, mul2(dca, lb))));

            float2 d = unpk2(det), n = unpk2(den);
            float ax0 = fabsf(n.x), ay0 = fabsf(d.x);
            float mx0 = fmaxf(ax0, ay0), mn0 = fminf(ax0, ay0);
            float t0 = (mx0 > 0.0f) ? __fdividef(mn0, mx0) : 0.0f;
            float ax1 = fabsf(n.y), ay1 = fabsf(d.y);
            float mx1 = fmaxf(ax1, ay1), mn1 = fminf(ax1, ay1);
            float t1 = (mx1 > 0.0f) ? __fdividef(mn1, mx1) : 0.0f;
            ull T = pk2(t0, t1);
            ull S = mul2(T, T);
            ull Pp = fma2(S, C4, C3);
            Pp = fma2(S, Pp, C2);
            Pp = fma2(S, Pp, C1);
            Pp = fma2(S, Pp, C0);
            Pp = fma2(S, Pp, CC);
            float2 r = unpk2(mul2(Pp, T));
            float r0 = r.x;
            if (ay0 > ax0)  r0 = 1.57079632679f - r0;
            if (n.x < 0.0f) r0 = 3.14159265359f - r0;
            if (d.x < 0.0f) r0 = -r0;
            float r1 = r.y;
            if (ay1 > ax1)  r1 = 1.57079632679f - r1;
            if (n.y < 0.0f) r1 = 3.14159265359f - r1;
            if (d.y < 0.0f) r1 = -r1;
            accA = add2(accA, pk2(r0, r1));
        }
        {
            ull ax = add2(tAx, nBx), ay = add2(tAy, nBy), az = add2(tAz, nBz);
            ull bx = add2(tBx, nBx), by = add2(tBy, nBy), bz = add2(tBz, nBz);
            ull cx = add2(tCx, nBx), cy = add2(tCy, nBy), cz = add2(tCz, nBz);
            ull a2 = fma2(ax, ax, fma2(ay, ay, mul2(az, az)));
            ull b2 = fma2(bx, bx, fma2(by, by, mul2(bz, bz)));
            ull c2 = fma2(cx, cx, fma2(cy, cy, mul2(cz, cz)));
            ull det = fma2(nBx, tnx, fma2(nBy, tny, fma2(nBz, tnz, td0)));
            ull dab = fma2(ax, bx, fma2(ay, by, mul2(az, bz)));
            ull dbc = fma2(bx, cx, fma2(by, cy, mul2(bz, cz)));
            ull dca = fma2(cx, ax, fma2(cy, ay, mul2(cz, az)));
            float2 a2s = unpk2(a2), b2s = unpk2(b2), c2s = unpk2(c2);
            ull la = pk2(sqrt_ap(a2s.x), sqrt_ap(a2s.y));
            ull lb = pk2(sqrt_ap(b2s.x), sqrt_ap(b2s.y));
            ull lc = pk2(sqrt_ap(c2s.x), sqrt_ap(c2s.y));
            ull den = fma2(mul2(la, lb), lc, fma2(dab, lc, fma2(dbc, la, mul2(dca, lb))));

            float2 d = unpk2(det), n = unpk2(den);
            float ax0 = fabsf(n.x), ay0 = fabsf(d.x);
            float mx0 = fmaxf(ax0, ay0), mn0 = fminf(ax0, ay0);
            float t0 = (mx0 > 0.0f) ? __fdividef(mn0, mx0) : 0.0f;
            float ax1 = fabsf(n.y), ay1 = fabsf(d.y);
            float mx1 = fmaxf(ax1, ay1), mn1 = fminf(ax1, ay1);
            float t1 = (mx1 > 0.0f) ? __fdividef(mn1, mx1) : 0.0f;
            ull T = pk2(t0, t1);
            ull S = mul2(T, T);
            ull Pp = fma2(S, C4, C3);
            Pp = fma2(S, Pp, C2);
            Pp = fma2(S, Pp, C1);
            Pp = fma2(S, Pp, C0);
            Pp = fma2(S, Pp, CC);
            float2 r = unpk2(mul2(Pp, T));
            float r0 = r.x;
            if (ay0 > ax0)  r0 = 1.57079632679f - r0;
            if (n.x < 0.0f) r0 = 3.14159265359f - r0;
            if (d.x < 0.0f) r0 = -r0;
            float r1 = r.y;
            if (ay1 > ax1)  r1 = 1.57079632679f - r1;
            if (n.y < 0.0f) r1 = 3.14159265359f - r1;
            if (d.y < 0.0f) r1 = -r1;
            accB = add2(accB, pk2(r0, r1));
        }
    }
    int base = seg * NMAX;
    float2 aA = unpk2(accA), aB = unpk2(accB);
    g_wpart[chunk][base + i0] = aA.x;
    g_wpart[chunk][base + i1] = aA.y;
    g_wpart[chunk][base + i2] = aB.x;
    if (ok3) g_wpart[chunk][base + i3] = aB.y;
}

// ---------------------------------------------------------
// stage-1 reduce: grid (NB1, 4 segs); per-block partial stats
// ---------------------------------------------------------
__global__ void __launch_bounds__(256)
reduce1_kernel(int N) {
    __shared__ float sh[8][4];
    const float INV2PI = 0.15915494309189535f;
    int seg = blockIdx.y;
    int per = (N + NB1 - 1) / NB1;
    int n0 = blockIdx.x * per;
    int n1 = min(N, n0 + per);
    int tid = threadIdx.x;
    int lane = tid & 31;
    int warp = tid >> 5;

    float mn = BIGF, mx = -BIGF, s = 0.0f, c = 0.0f;
    for (int n = n0 + tid; n < n1; n += 256) {
        int ia = seg * NMAX + n;
        float w = 0.0f, ms = BIGF;
        #pragma unroll
        for (int ch = 0; ch < WCH; ch++) w += g_wpart[ch][ia];
        #pragma unroll
        for (int ch = 0; ch < MCH; ch++) ms = fminf(ms, g_mpart[ch][ia]);
        float rm = sqrtf(fmaxf(ms, 0.0f));
        mn = fminf(mn, rm);
        if (w * INV2PI >= 0.99f) { mx = fmaxf(mx, rm); s += rm; c += 1.0f; }
    }
    #pragma unroll
    for (int o = 16; o; o >>= 1) {
        mn = fminf(mn, __shfl_xor_sync(0xffffffffu, mn, o));
        mx = fmaxf(mx, __shfl_xor_sync(0xffffffffu, mx, o));
        s +=           __shfl_xor_sync(0xffffffffu, s,  o);
        c +=           __shfl_xor_sync(0xffffffffu, c,  o);
    }
    if (lane == 0) { sh[warp][0] = mn; sh[warp][1] = mx; sh[warp][2] = s; sh[warp][3] = c; }
    __syncthreads();
    if (tid == 0) {
        #pragma unroll
        for (int w = 1; w < 8; w++) {
            mn = fminf(mn, sh[w][0]);
            mx = fmaxf(mx, sh[w][1]);
            s += sh[w][2];
            c += sh[w][3];
        }
        g_red[seg][blockIdx.x] = make_float4(mn, mx, s, c);
    }
}

// ---------------------------------------------------------
// stage-2 reduce: 4 warps, one per seg; lanes over NB1 blocks
// out layout: [5][B] row-major
// ---------------------------------------------------------
__global__ void __launch_bounds__(128)
reduce2_kernel(float* __restrict__ out) {
    __shared__ float sh[4][4];
    int tid = threadIdx.x;
    int lane = tid & 31;
    int seg = tid >> 5;

    float4 v = g_red[seg][lane];   // NB1 == 32
    float mn = v.x, mx = v.y, s = v.z, c = v.w;
    #pragma unroll
    for (int o = 16; o; o >>= 1) {
        mn = fminf(mn, __shfl_xor_sync(0xffffffffu, mn, o));
        mx = fmaxf(mx, __shfl_xor_sync(0xffffffffu, mx, o));
        s +=           __shfl_xor_sync(0xffffffffu, s,  o);
        c +=           __shfl_xor_sync(0xffffffffu, c,  o);
    }
    if (lane == 0) { sh[seg][0] = mn; sh[seg][1] = mx; sh[seg][2] = s; sh[seg][3] = c; }
    __syncthreads();
    if (tid < B_) {
        int b = tid;
        float mn0 = sh[b][0];
        float mx1 = sh[b][1], s1 = sh[b][2], c1 = sh[b][3];
        float mx2 = sh[2 + b][1], s2 = sh[2 + b][2], c2 = sh[2 + b][3];
        out[0 * B_ + b] = mn0;
        out[1 * B_ + b] = (c1 > 0.0f) ? mx1 : 0.0f;
        out[2 * B_ + b] = (c1 > 0.0f) ? s1 / fmaxf(c1, 1.0f) : 0.0f;
        out[3 * B_ + b] = (c2 > 0.0f) ? mx2 : 0.0f;
        out[4 * B_ + b] = (c2 > 0.0f) ? s2 / fmaxf(c2, 1.0f) : 0.0f;
    }
}

// ---------------------------------------------------------
extern "C" void kernel_launch(void* const* d_in, const int* in_sizes, int n_in,
                              void* d_out, int out_size) {
    const float* v1 = (const float*)d_in[0];
    const float* v2 = (const float*)d_in[1];
    const int* faces = (const int*)d_in[2];
    float* out = (float*)d_out;

    int N = in_sizes[0] / (3 * B_);   // 6890
    int NF = in_sizes[2] / 3;         // 2000

    // launches 1-2: gather (split so winding is the 4th launch, the ncu slot)
    gather_pts_kernel<<<(B_ * N + 255) / 256, 256>>>(v1, v2, N);
    gather_tri_kernel<<<(B_ * NF + 255) / 256, 256>>>(v1, v2, faces, N, NF);

    // launch 3: minsq (single launch, 224 blocks)
    int Q = (N + 3) >> 2;
    dim3 mgrid((Q + 255) / 256, 4 * MCH);
    minsq_kernel<<<mgrid, 256>>>(N);

    // launch 4: winding
    int H4 = (N + 3) >> 2;
    dim3 wgrid((H4 + 255) / 256, 4 * WCH);
    winding_kernel<<<wgrid, 256>>>(N, NF);

    dim3 rgrid(NB1, 4);
    reduce1_kernel<<<rgrid, 256>>>(N);
    reduce2_kernel<<<1, 128>>>(out);
}

// round 6
// speedup vs baseline: 1.6300x; 1.3553x over previous
#include <cuda_runtime.h>
#include <math.h>

// Problem constants (fixed by setup_inputs): B=2, N=6890, NF=2000
#define B_    2
#define NMAX  7168
#define NFMAX 2048
#define WCH   21       // triangle chunks for winding  (7*4*21 = 588 blocks)
#define WFPC  96       // max tris per chunk staged in smem (ceil(2000/21))
#define MCH   21       // point chunks for minsq       (7*4*21 = 588 blocks)
#define NB1   32       // stage-1 reduce blocks per segment
#define BIGF  3.4e38f

typedef unsigned long long ull;

// -------- device scratch (no allocations allowed) --------
__device__ float4 g_pts4[2][B_ * NMAX];            // (x,y,z,|p|^2)
// triangles SoA: [src][ (b*13 + comp)*NFMAX + f ]
// comps: 0-2 A, 3-5 B, 6-8 C, 9-11 n=(B-A)x(C-A), 12 d0=A.n
__device__ float g_triS[2][B_ * 13 * NFMAX];
__device__ float g_wpart[WCH][4 * NMAX];           // partial atan2 sums
__device__ float g_mpart[MCH][4 * NMAX];           // partial sq-dist mins
__device__ float4 g_red[4][NB1];                   // (mn, mx, sum, cnt)

// ---------------- packed f32x2 helpers (sm_100+) ----------------
__device__ __forceinline__ ull pk2(float lo, float hi) {
    ull r;
    asm("mov.b64 %0, {%1, %2};" : "=l"(r)
        : "r"(__float_as_uint(lo)), "r"(__float_as_uint(hi)));
    return r;
}
__device__ __forceinline__ float2 unpk2(ull v) {
    unsigned int lo, hi;
    asm("mov.b64 {%0, %1}, %2;" : "=r"(lo), "=r"(hi) : "l"(v));
    return make_float2(__uint_as_float(lo), __uint_as_float(hi));
}
__device__ __forceinline__ ull fma2(ull a, ull b, ull c) {
    ull d; asm("fma.rn.f32x2 %0, %1, %2, %3;" : "=l"(d) : "l"(a), "l"(b), "l"(c)); return d;
}
__device__ __forceinline__ ull add2(ull a, ull b) {
    ull d; asm("add.rn.f32x2 %0, %1, %2;" : "=l"(d) : "l"(a), "l"(b)); return d;
}
__device__ __forceinline__ ull mul2(ull a, ull b) {
    ull d; asm("mul.rn.f32x2 %0, %1, %2;" : "=l"(d) : "l"(a), "l"(b)); return d;
}
__device__ __forceinline__ float sqrt_ap(float x) {
    float r; asm("sqrt.approx.f32 %0, %1;" : "=f"(r) : "f"(x)); return r;
}

// ---------------------------------------------------------
// gather A: float4 points (with |p|^2)
// ---------------------------------------------------------
__global__ void gather_pts_kernel(const float* __restrict__ v1,
                                  const float* __restrict__ v2,
                                  int N) {
    int stride = gridDim.x * blockDim.x;
    int t0 = blockIdx.x * blockDim.x + threadIdx.x;
    int PT = B_ * N;
    for (int i = t0; i < PT; i += stride) {
        float x = v1[i * 3 + 0], y = v1[i * 3 + 1], z = v1[i * 3 + 2];
        g_pts4[0][i] = make_float4(x, y, z, fmaf(x, x, fmaf(y, y, z * z)));
        x = v2[i * 3 + 0]; y = v2[i * 3 + 1]; z = v2[i * 3 + 2];
        g_pts4[1][i] = make_float4(x, y, z, fmaf(x, x, fmaf(y, y, z * z)));
    }
}

// ---------------------------------------------------------
// gather B: triangle SoA + normal + d0
// ---------------------------------------------------------
__global__ void gather_tri_kernel(const float* __restrict__ v1,
                                  const float* __restrict__ v2,
                                  const int*   __restrict__ faces,
                                  int N, int NF) {
    int stride = gridDim.x * blockDim.x;
    int t0 = blockIdx.x * blockDim.x + threadIdx.x;
    int FT = B_ * NF;
    for (int i = t0; i < FT; i += stride) {
        int b = i / NF;
        int f = i - b * NF;
        int i0 = faces[f * 3 + 0];
        int i1 = faces[f * 3 + 1];
        int i2 = faces[f * 3 + 2];
        int base = b * N * 3;
        #pragma unroll
        for (int s = 0; s < 2; s++) {
            const float* v = (s == 0) ? v1 : v2;
            float Ax = v[base + i0 * 3 + 0], Ay = v[base + i0 * 3 + 1], Az = v[base + i0 * 3 + 2];
            float Bx = v[base + i1 * 3 + 0], By = v[base + i1 * 3 + 1], Bz = v[base + i1 * 3 + 2];
            float Cx = v[base + i2 * 3 + 0], Cy = v[base + i2 * 3 + 1], Cz = v[base + i2 * 3 + 2];
            float ex = Bx - Ax, ey = By - Ay, ez = Bz - Az;
            float fx = Cx - Ax, fy = Cy - Ay, fz = Cz - Az;
            float nx = fmaf(ey, fz, -ez * fy);
            float ny = fmaf(ez, fx, -ex * fz);
            float nz = fmaf(ex, fy, -ey * fx);
            float d0 = fmaf(Ax, nx, fmaf(Ay, ny, Az * nz));
            float* T = g_triS[s] + (size_t)(b * 13) * NFMAX + f;
            T[0 * NFMAX] = Ax;  T[1 * NFMAX] = Ay;  T[2 * NFMAX] = Az;
            T[3 * NFMAX] = Bx;  T[4 * NFMAX] = By;  T[5 * NFMAX] = Bz;
            T[6 * NFMAX] = Cx;  T[7 * NFMAX] = Cy;  T[8 * NFMAX] = Cz;
            T[9 * NFMAX] = nx;  T[10 * NFMAX] = ny; T[11 * NFMAX] = nz;
            T[12 * NFMAX] = d0;
        }
    }
}

// ---------------------------------------------------------
// minsq: 4 scalar points per thread vs packed pairs of q.
// grid: x covers Q=ceil(N/4), y = seg*MCH + chunk (seg = dir*2+b)
// ---------------------------------------------------------
__global__ void __launch_bounds__(256)
minsq_kernel(int N) {
    int yc = blockIdx.y;
    int seg = yc / MCH;
    int chunk = yc - seg * MCH;
    int dir = seg >> 1;
    int b = seg & 1;
    int Q = (N + 3) >> 2;
    int t = blockIdx.x * 256 + threadIdx.x;
    if (t >= Q) return;

    const float4* __restrict__ P = g_pts4[dir] + b * N;
    const float4* __restrict__ O = g_pts4[1 - dir] + b * N;

    int i0 = t, i1 = t + Q, i2 = t + 2 * Q, i3 = t + 3 * Q;
    bool ok3 = (i3 < N);
    float4 p0 = P[i0];
    float4 p1 = P[i1];
    float4 p2 = P[i2];
    float4 p3 = ok3 ? P[i3] : p2;

    ull p0x = pk2(p0.x, p0.x), p0y = pk2(p0.y, p0.y), p0z = pk2(p0.z, p0.z);
    ull p1x = pk2(p1.x, p1.x), p1y = pk2(p1.y, p1.y), p1z = pk2(p1.z, p1.z);
    ull p2x = pk2(p2.x, p2.x), p2y = pk2(p2.y, p2.y), p2z = pk2(p2.z, p2.z);
    ull p3x = pk2(p3.x, p3.x), p3y = pk2(p3.y, p3.y), p3z = pk2(p3.z, p3.z);
    ull m2  = pk2(-2.0f, -2.0f);

    int mpc = (N + MCH - 1) / MCH;
    int m0 = chunk * mpc;
    int m1 = min(N, m0 + mpc);

    float b0 = BIGF, b1v = BIGF, b2v = BIGF, b3v = BIGF;
    int m = m0;
    for (; m + 1 < m1; m += 2) {
        float4 qa = O[m];
        float4 qb = O[m + 1];
        ull qx = pk2(qa.x, qb.x);
        ull qy = pk2(qa.y, qb.y);
        ull qz = pk2(qa.z, qb.z);
        ull qw = pk2(qa.w, qb.w);

        ull d0 = fma2(p0x, qx, fma2(p0y, qy, mul2(p0z, qz)));
        ull d1 = fma2(p1x, qx, fma2(p1y, qy, mul2(p1z, qz)));
        ull d2 = fma2(p2x, qx, fma2(p2y, qy, mul2(p2z, qz)));
        ull d3 = fma2(p3x, qx, fma2(p3y, qy, mul2(p3z, qz)));
        float2 v0 = unpk2(fma2(m2, d0, qw));
        float2 v1 = unpk2(fma2(m2, d1, qw));
        float2 v2 = unpk2(fma2(m2, d2, qw));
        float2 v3 = unpk2(fma2(m2, d3, qw));
        b0  = fminf(b0,  fminf(v0.x, v0.y));
        b1v = fminf(b1v, fminf(v1.x, v1.y));
        b2v = fminf(b2v, fminf(v2.x, v2.y));
        b3v = fminf(b3v, fminf(v3.x, v3.y));
    }
    for (; m < m1; ++m) {
        float4 q = O[m];
        float d0 = fmaf(p0.x, q.x, fmaf(p0.y, q.y, p0.z * q.z));
        float d1 = fmaf(p1.x, q.x, fmaf(p1.y, q.y, p1.z * q.z));
        float d2 = fmaf(p2.x, q.x, fmaf(p2.y, q.y, p2.z * q.z));
        float d3 = fmaf(p3.x, q.x, fmaf(p3.y, q.y, p3.z * q.z));
        b0  = fminf(b0,  fmaf(-2.0f, d0, q.w));
        b1v = fminf(b1v, fmaf(-2.0f, d1, q.w));
        b2v = fminf(b2v, fmaf(-2.0f, d2, q.w));
        b3v = fminf(b3v, fmaf(-2.0f, d3, q.w));
    }
    int base = seg * NMAX;
    g_mpart[chunk][base + i0] = b0 + p0.w;
    g_mpart[chunk][base + i1] = b1v + p1.w;
    g_mpart[chunk][base + i2] = b2v + p2.w;
    if (ok3) g_mpart[chunk][base + i3] = b3v + p3.w;
}

// ---------------------------------------------------------
// packed solid-angle term for one point-pair vs one triangle.
// np* = packed negated point coords. Returns packed atan2 values.
// ---------------------------------------------------------
__device__ __forceinline__ ull pair_term(
    ull npx, ull npy, ull npz,
    ull tAx, ull tAy, ull tAz,
    ull tBx, ull tBy, ull tBz,
    ull tCx, ull tCy, ull tCz,
    ull tnx, ull tny, ull tnz, ull td0,
    ull C4, ull C3, ull C2, ull C1, ull C0, ull CC)
{
    ull ax = add2(tAx, npx), ay = add2(tAy, npy), az = add2(tAz, npz);
    ull bx = add2(tBx, npx), by = add2(tBy, npy), bz = add2(tBz, npz);
    ull cx = add2(tCx, npx), cy = add2(tCy, npy), cz = add2(tCz, npz);

    ull a2 = fma2(ax, ax, fma2(ay, ay, mul2(az, az)));
    ull b2 = fma2(bx, bx, fma2(by, by, mul2(bz, bz)));
    ull c2 = fma2(cx, cx, fma2(cy, cy, mul2(cz, cz)));

    ull det = fma2(npx, tnx, fma2(npy, tny, fma2(npz, tnz, td0)));

    ull dab = fma2(ax, bx, fma2(ay, by, mul2(az, bz)));
    ull dbc = fma2(bx, cx, fma2(by, cy, mul2(bz, cz)));
    ull dca = fma2(cx, ax, fma2(cy, ay, mul2(cz, az)));

    float2 a2s = unpk2(a2), b2s = unpk2(b2), c2s = unpk2(c2);
    ull la = pk2(sqrt_ap(a2s.x), sqrt_ap(a2s.y));
    ull lb = pk2(sqrt_ap(b2s.x), sqrt_ap(b2s.y));
    ull lc = pk2(sqrt_ap(c2s.x), sqrt_ap(c2s.y));

    ull den = fma2(mul2(la, lb), lc,
              fma2(dab, lc,
              fma2(dbc, la, mul2(dca, lb))));

    // range reduction (scalar; abs folds into FMNMX modifiers)
    float2 d = unpk2(det), n = unpk2(den);
    float ax0 = fabsf(n.x), ay0 = fabsf(d.x);
    float mx0 = fmaxf(ax0, ay0), mn0 = fminf(ax0, ay0);
    float t0 = __fdividef(mn0, fmaxf(mx0, 1e-37f));
    float ax1 = fabsf(n.y), ay1 = fabsf(d.y);
    float mx1 = fmaxf(ax1, ay1), mn1 = fminf(ax1, ay1);
    float t1 = __fdividef(mn1, fmaxf(mx1, 1e-37f));

    // packed polynomial
    ull T = pk2(t0, t1);
    ull S = mul2(T, T);
    ull Pp = fma2(S, C4, C3);
    Pp = fma2(S, Pp, C2);
    Pp = fma2(S, Pp, C1);
    Pp = fma2(S, Pp, C0);
    Pp = fma2(S, Pp, CC);
    float2 r = unpk2(mul2(Pp, T));

    // quadrant fixups (scalar)
    float r0 = r.x;
    if (ay0 > ax0)  r0 = 1.57079632679f - r0;
    if (n.x < 0.0f) r0 = 3.14159265359f - r0;
    if (d.x < 0.0f) r0 = -r0;
    float r1 = r.y;
    if (ay1 > ax1)  r1 = 1.57079632679f - r1;
    if (n.y < 0.0f) r1 = 3.14159265359f - r1;
    if (d.y < 0.0f) r1 = -r1;
    return pk2(r0, r1);
}

// ---------------------------------------------------------
// winding: 4 points per thread as two f32x2 pairs; triangle chunk
// staged in smem as duplicated (v,v) pairs (LDS.64 operands).
// grid: x covers H4=ceil(N/4), y = seg*WCH + chunk (seg = dir*2+b)
// ---------------------------------------------------------
__global__ void __launch_bounds__(256)
winding_kernel(int N, int NF) {
    __shared__ ull smT[13][WFPC];

    int yc = blockIdx.y;
    int seg = yc / WCH;
    int chunk = yc - seg * WCH;
    int dir = seg >> 1;
    int b = seg & 1;
    int H4 = (N + 3) >> 2;
    int t = blockIdx.x * 256 + threadIdx.x;

    int src = 1 - dir;
    int fpc = (NF + WCH - 1) / WCH;
    int f0 = chunk * fpc;
    int f1 = min(NF, f0 + fpc);
    int nf = f1 - f0;           // <= WFPC

    // cooperative stage: duplicated-pair layout
    {
        const float* Tb = g_triS[src] + (size_t)(b * 13) * NFMAX + f0;
        #pragma unroll
        for (int c = 0; c < 13; c++) {
            for (int j = threadIdx.x; j < nf; j += 256) {
                float v = Tb[c * NFMAX + j];
                smT[c][j] = pk2(v, v);
            }
        }
    }
    __syncthreads();

    if (t >= H4) return;

    const float4* __restrict__ P = g_pts4[dir] + b * N;
    int i0 = t, i1 = t + H4, i2 = t + 2 * H4, i3 = t + 3 * H4;
    bool ok3 = (i3 < N);
    float4 p0 = P[i0];
    float4 p1 = P[i1];
    float4 p2 = P[i2];
    float4 p3 = ok3 ? P[i3] : p2;

    ull nAx = pk2(-p0.x, -p1.x), nAy = pk2(-p0.y, -p1.y), nAz = pk2(-p0.z, -p1.z);
    ull nBx = pk2(-p2.x, -p3.x), nBy = pk2(-p2.y, -p3.y), nBz = pk2(-p2.z, -p3.z);

    ull C4 = pk2(-0.01172120f, -0.01172120f);
    ull C3 = pk2( 0.05265332f,  0.05265332f);
    ull C2 = pk2(-0.11643287f, -0.11643287f);
    ull C1 = pk2( 0.19354346f,  0.19354346f);
    ull C0 = pk2(-0.33262347f, -0.33262347f);
    ull CC = pk2( 0.99997726f,  0.99997726f);

    ull accA = 0, accB = 0;
    for (int j = 0; j < nf; ++j) {
        ull tAx = smT[0][j], tAy = smT[1][j], tAz = smT[2][j];
        ull tBx = smT[3][j], tBy = smT[4][j], tBz = smT[5][j];
        ull tCx = smT[6][j], tCy = smT[7][j], tCz = smT[8][j];
        ull tnx = smT[9][j], tny = smT[10][j], tnz = smT[11][j];
        ull td0 = smT[12][j];

        accA = add2(accA, pair_term(nAx, nAy, nAz, tAx, tAy, tAz,
                                    tBx, tBy, tBz, tCx, tCy, tCz,
                                    tnx, tny, tnz, td0,
                                    C4, C3, C2, C1, C0, CC));
        accB = add2(accB, pair_term(nBx, nBy, nBz, tAx, tAy, tAz,
                                    tBx, tBy, tBz, tCx, tCy, tCz,
                                    tnx, tny, tnz, td0,
                                    C4, C3, C2, C1, C0, CC));
    }
    int base = seg * NMAX;
    float2 aA = unpk2(accA), aB = unpk2(accB);
    g_wpart[chunk][base + i0] = aA.x;
    g_wpart[chunk][base + i1] = aA.y;
    g_wpart[chunk][base + i2] = aB.x;
    if (ok3) g_wpart[chunk][base + i3] = aB.y;
}

// ---------------------------------------------------------
// stage-1 reduce: grid (NB1, 4 segs); per-block partial stats
// ---------------------------------------------------------
__global__ void __launch_bounds__(256)
reduce1_kernel(int N) {
    __shared__ float sh[8][4];
    const float INV2PI = 0.15915494309189535f;
    int seg = blockIdx.y;
    int per = (N + NB1 - 1) / NB1;
    int n0 = blockIdx.x * per;
    int n1 = min(N, n0 + per);
    int tid = threadIdx.x;
    int lane = tid & 31;
    int warp = tid >> 5;

    float mn = BIGF, mx = -BIGF, s = 0.0f, c = 0.0f;
    for (int n = n0 + tid; n < n1; n += 256) {
        int ia = seg * NMAX + n;
        float w = 0.0f, ms = BIGF;
        #pragma unroll
        for (int ch = 0; ch < WCH; ch++) w += g_wpart[ch][ia];
        #pragma unroll
        for (int ch = 0; ch < MCH; ch++) ms = fminf(ms, g_mpart[ch][ia]);
        float rm = sqrtf(fmaxf(ms, 0.0f));
        mn = fminf(mn, rm);
        if (w * INV2PI >= 0.99f) { mx = fmaxf(mx, rm); s += rm; c += 1.0f; }
    }
    #pragma unroll
    for (int o = 16; o; o >>= 1) {
        mn = fminf(mn, __shfl_xor_sync(0xffffffffu, mn, o));
        mx = fmaxf(mx, __shfl_xor_sync(0xffffffffu, mx, o));
        s +=           __shfl_xor_sync(0xffffffffu, s,  o);
        c +=           __shfl_xor_sync(0xffffffffu, c,  o);
    }
    if (lane == 0) { sh[warp][0] = mn; sh[warp][1] = mx; sh[warp][2] = s; sh[warp][3] = c; }
    __syncthreads();
    if (tid == 0) {
        #pragma unroll
        for (int w = 1; w < 8; w++) {
            mn = fminf(mn, sh[w][0]);
            mx = fmaxf(mx, sh[w][1]);
            s += sh[w][2];
            c += sh[w][3];
        }
        g_red[seg][blockIdx.x] = make_float4(mn, mx, s, c);
    }
}

// ---------------------------------------------------------
// stage-2 reduce: 4 warps, one per seg; lanes over NB1 blocks
// out layout: [5][B] row-major
// ---------------------------------------------------------
__global__ void __launch_bounds__(128)
reduce2_kernel(float* __restrict__ out) {
    __shared__ float sh[4][4];
    int tid = threadIdx.x;
    int lane = tid & 31;
    int seg = tid >> 5;

    float4 v = g_red[seg][lane];   // NB1 == 32
    float mn = v.x, mx = v.y, s = v.z, c = v.w;
    #pragma unroll
    for (int o = 16; o; o >>= 1) {
        mn = fminf(mn, __shfl_xor_sync(0xffffffffu, mn, o));
        mx = fmaxf(mx, __shfl_xor_sync(0xffffffffu, mx, o));
        s +=           __shfl_xor_sync(0xffffffffu, s,  o);
        c +=           __shfl_xor_sync(0xffffffffu, c,  o);
    }
    if (lane == 0) { sh[seg][0] = mn; sh[seg][1] = mx; sh[seg][2] = s; sh[seg][3] = c; }
    __syncthreads();
    if (tid < B_) {
        int b = tid;
        float mn0 = sh[b][0];
        float mx1 = sh[b][1], s1 = sh[b][2], c1 = sh[b][3];
        float mx2 = sh[2 + b][1], s2 = sh[2 + b][2], c2 = sh[2 + b][3];
        out[0 * B_ + b] = mn0;
        out[1 * B_ + b] = (c1 > 0.0f) ? mx1 : 0.0f;
        out[2 * B_ + b] = (c1 > 0.0f) ? s1 / fmaxf(c1, 1.0f) : 0.0f;
        out[3 * B_ + b] = (c2 > 0.0f) ? mx2 : 0.0f;
        out[4 * B_ + b] = (c2 > 0.0f) ? s2 / fmaxf(c2, 1.0f) : 0.0f;
    }
}

// ---------------------------------------------------------
extern "C" void kernel_launch(void* const* d_in, const int* in_sizes, int n_in,
                              void* d_out, int out_size) {
    const float* v1 = (const float*)d_in[0];
    const float* v2 = (const float*)d_in[1];
    const int* faces = (const int*)d_in[2];
    float* out = (float*)d_out;

    int N = in_sizes[0] / (3 * B_);   // 6890
    int NF = in_sizes[2] / 3;         // 2000

    // launches 1-2: gather (split so winding is the 4th launch, the ncu slot)
    gather_pts_kernel<<<(B_ * N + 255) / 256, 256>>>(v1, v2, N);
    gather_tri_kernel<<<(B_ * NF + 255) / 256, 256>>>(v1, v2, faces, N, NF);

    // launch 3: minsq (588 blocks)
    int Q = (N + 3) >> 2;
    dim3 mgrid((Q + 255) / 256, 4 * MCH);
    minsq_kernel<<<mgrid, 256>>>(N);

    // launch 4: winding (588 blocks ~ full single-wave residency)
    int H4 = (N + 3) >> 2;
    dim3 wgrid((H4 + 255) / 256, 4 * WCH);
    winding_kernel<<<wgrid, 256>>>(N, NF);

    dim3 rgrid(NB1, 4);
    reduce1_kernel<<<rgrid, 256>>>(N);
    reduce2_kernel<<<1, 128>>>(out);
}